// round 13
// baseline (speedup 1.0000x reference)
#include <cuda_runtime.h>
#include <cuda_bf16.h>
#include <cstdint>

// VectorQuantizer: single-pass bf16 MMA screen with d~ stored to smem (bf16),
// branch-light margin scan, certified exact fp32 rescore (R1-replica, bit-exact).

#define NTOK   131072
#define DDIM   64
#define KCODE  512
#define HWSZ   4096
#define CHW    (64*4096)
#define NELEM  (NTOK*DDIM)

#define TILE      64
#define NSUB      2048
#define GRID_GEMM 148
#define THR       256
#define MARGIN    4e-3f
#define CAP       24
#define DTSTR     1040        // DT row stride bytes (512*2 + 16 pad)

// ---- dynamic smem layout (bytes) ----
#define SM_BF    0            // B frags: 8192 x uint2 = 65536
#define SM_XF    65536        // X fp32: 64 x 264B = 16896
#define SM_DT    82432        // d~ bf16: 64 x 1040 = 66560
#define SM_NS    148992       // ns fp32[512] = 2048
#define SM_RMIN  151040       // float[64][2] = 512
#define SM_CNT   151552       // int[64] = 256
#define SM_LST   151808       // int[64][CAP] = 6144
#define SM_AA    157952       // float[64] = 256
#define SM_RB    158208       // float[256] = 1024
#define SM_RK    159232       // int[256] = 1024
#define SM_TOTAL 160256

__device__ int    g_idx[NTOK];
__device__ int    g_counts[KCODE];
__device__ double g_sumsq;

__device__ __forceinline__ uint32_t pkbf(float a, float b) {
    __nv_bfloat162 t = __floats2bfloat162_rn(a, b);
    uint32_t u; memcpy(&u, &t, 4);
    return u;
}
__device__ __forceinline__ float2 bf2f(uint32_t u) {
    __nv_bfloat162 h; memcpy(&h, &u, 4);
    return __bfloat1622float2(h);
}
__device__ __forceinline__ unsigned long long pack2(float lo, float hi) {
    unsigned long long r;
    asm("mov.b64 %0, {%1,%2};" : "=l"(r) : "f"(lo), "f"(hi));
    return r;
}
__device__ __forceinline__ void fma2(unsigned long long& d, unsigned long long a, unsigned long long b) {
    asm("fma.rn.f32x2 %0, %1, %2, %0;" : "+l"(d) : "l"(a), "l"(b));
}
__device__ __forceinline__ float2 unpack2(unsigned long long v) {
    float lo, hi;
    asm("mov.b64 {%0,%1}, %2;" : "=f"(lo), "=f"(hi) : "l"(v));
    return make_float2(lo, hi);
}
__device__ __forceinline__ void mma16816(float* c, const uint32_t* a, uint32_t b0, uint32_t b1) {
    asm volatile(
        "mma.sync.aligned.m16n8k16.row.col.f32.bf16.bf16.f32 "
        "{%0,%1,%2,%3}, {%4,%5,%6,%7}, {%8,%9}, {%0,%1,%2,%3};"
        : "+f"(c[0]), "+f"(c[1]), "+f"(c[2]), "+f"(c[3])
        : "r"(a[0]), "r"(a[1]), "r"(a[2]), "r"(a[3]), "r"(b0), "r"(b1));
}

// EXACT distance, replicating R1's instruction sequence (validated R6/R10).
__device__ __forceinline__ float exact_dist(const float2* __restrict__ xr,
                                            const float* __restrict__ w,
                                            int k, float aa, float nk) {
    const float2* wr = (const float2*)(w + k * DDIM);
    unsigned long long a0 = 0ull, a1 = 0ull, a2 = 0ull, a3 = 0ull;
#pragma unroll
    for (int j = 0; j < 8; j++) {
        float2 x0 = xr[4*j+0], x1 = xr[4*j+1], x2 = xr[4*j+2], x3 = xr[4*j+3];
        float2 w0 = wr[4*j+0], w1 = wr[4*j+1], w2 = wr[4*j+2], w3 = wr[4*j+3];
        fma2(a0, pack2(x0.x, x0.y), pack2(w0.x, w0.y));
        fma2(a1, pack2(x1.x, x1.y), pack2(w1.x, w1.y));
        fma2(a2, pack2(x2.x, x2.y), pack2(w2.x, w2.y));
        fma2(a3, pack2(x3.x, x3.y), pack2(w3.x, w3.y));
    }
    float2 f0 = unpack2(a0), f1 = unpack2(a1), f2 = unpack2(a2), f3 = unpack2(a3);
    float m = ((f0.x + f0.y) + (f1.x + f1.y)) + ((f2.x + f2.y) + (f3.x + f3.y));
    return (aa - 2.0f * m) + nk;
}

__global__ void vq_init() {
    int t = threadIdx.x;
    if (t < KCODE) g_counts[t] = 0;
    if (t == 0)    g_sumsq = 0.0;
}

extern __shared__ char smem[];

__global__ __launch_bounds__(THR, 1) void vq_gemm(const float* __restrict__ in,
                                                  const float* __restrict__ w) {
    const int tid  = threadIdx.x;
    const int warp = tid >> 5;
    const int lane = tid & 31;

    // ---- one-time staging: ns + bf16 B fragments ----
    {
        float* ns = (float*)(smem + SM_NS);
#pragma unroll
        for (int cc = 0; cc < 2; cc++) {
            int c = tid + cc * 256;
            const float4* wr = (const float4*)(w + c * DDIM);
            float nrm = 0.f;
#pragma unroll
            for (int j = 0; j < 16; j++) {
                float4 v = wr[j];
                nrm = fmaf(v.x, v.x, nrm); nrm = fmaf(v.y, v.y, nrm);
                nrm = fmaf(v.z, v.z, nrm); nrm = fmaf(v.w, v.w, nrm);
            }
            ns[c] = nrm;
        }
#pragma unroll
        for (int j = 0; j < 32; j++) {
            int idx = j * 256 + tid;            // nbg*128 + kt*32 + ln
            int ln  = idx & 31;
            int kt  = (idx >> 5) & 3;
            int nbg = idx >> 7;
            int n   = nbg * 8 + (ln >> 2);
            int k0  = kt * 16 + (ln & 3) * 2;
            float2 fa = *(const float2*)(w + n * DDIM + k0);
            float2 fb = *(const float2*)(w + n * DDIM + k0 + 8);
            uint2 fr;
            fr.x = pkbf(fa.x, fa.y);
            fr.y = pkbf(fb.x, fb.y);
            *(uint2*)(smem + SM_BF + (size_t)idx * 8) = fr;
        }
    }
    __syncthreads();

    const int m    = tid & 63;       // gather row
    const int qq   = tid >> 6;       // gather dim quarter
    const int wq   = warp & 3;       // warp row group
    const int side = warp >> 2;      // warp col half (0: 0..255, 1: 256..511)
    const int r0   = wq * 16 + (lane >> 2);   // rows r0, r0+8

    const float* nsf = (const float*)(smem + SM_NS);
    float* rmin = (float*)(smem + SM_RMIN);
    int*   cnt  = (int*)(smem + SM_CNT);
    int*   lst  = (int*)(smem + SM_LST);
    float* aar  = (float*)(smem + SM_AA);
    float* rb   = (float*)(smem + SM_RB);
    int*   rk   = (int*)(smem + SM_RK);

    for (int t = blockIdx.x; t < NSUB; t += GRID_GEMM) {
        __syncthreads();   // prev subtile fully consumed

        // ---- gather 64 tokens x 64 dims (fp32, exact) ----
        {
            const int b   = t >> 6;
            const int hw0 = (t & 63) << 6;
            const float* base = in + b * CHW + hw0 + m;
            char* pf = smem + SM_XF + m * 264;
#pragma unroll
            for (int j = 0; j < 16; j += 2) {
                int d = qq * 16 + j;
                float x0 = base[d * HWSZ];
                float x1 = base[(d + 1) * HWSZ];
                *(float2*)(pf + d * 4) = make_float2(x0, x1);
            }
            if (tid < TILE) cnt[tid] = 0;
        }
        __syncthreads();

        // ---- exact ||x||^2 (R1 serial order) overlapped with MMA setup ----
        if (tid < TILE) {
            const float2* xr = (const float2*)(smem + SM_XF + tid * 264);
            float aa = 0.f;
#pragma unroll
            for (int j = 0; j < 32; j++) {
                float2 v = xr[j];
                aa = fmaf(v.x, v.x, aa);
                aa = fmaf(v.y, v.y, aa);
            }
            aar[tid] = aa;
        }

        // ---- A fragments from fp32 X (cvt in regs) ----
        uint32_t ah[16];
        {
            const char* pxa = smem + SM_XF + r0 * 264 + (lane & 3) * 8;
#pragma unroll
            for (int kt = 0; kt < 4; kt++) {
                float2 v0 = *(const float2*)(pxa + kt * 64);
                float2 v1 = *(const float2*)(pxa + kt * 64 + 8 * 264);
                float2 v2 = *(const float2*)(pxa + kt * 64 + 32);
                float2 v3 = *(const float2*)(pxa + kt * 64 + 8 * 264 + 32);
                ah[kt*4+0] = pkbf(v0.x, v0.y);
                ah[kt*4+1] = pkbf(v1.x, v1.y);
                ah[kt*4+2] = pkbf(v2.x, v2.y);
                ah[kt*4+3] = pkbf(v3.x, v3.y);
            }
        }

        // ---- single MMA pass: min + store d~ (bf16) ----
        float dmin0 = 3.4e38f, dmin1 = 3.4e38f;
#pragma unroll 4
        for (int nb = 0; nb < 32; nb++) {
            int nbg = side * 32 + nb;
            float c[4] = {0.f, 0.f, 0.f, 0.f};
            const char* fp = smem + SM_BF + ((size_t)(nbg * 128) + lane) * 8;
#pragma unroll
            for (int kt = 0; kt < 4; kt++) {
                uint2 f = *(const uint2*)(fp + kt * 256);
                mma16816(c, ah + kt*4, f.x, f.y);
            }
            int cb = nbg * 8 + (lane & 3) * 2;
            float2 nn = *(const float2*)(smem + SM_NS + cb * 4);
            float d0 = fmaf(-2.f, c[0], nn.x), d1 = fmaf(-2.f, c[1], nn.y);
            float d2 = fmaf(-2.f, c[2], nn.x), d3 = fmaf(-2.f, c[3], nn.y);
            dmin0 = fminf(dmin0, fminf(d0, d1));
            dmin1 = fminf(dmin1, fminf(d2, d3));
            char* dtp = smem + SM_DT + r0 * DTSTR + cb * 2;
            *(uint32_t*)dtp               = pkbf(d0, d1);
            *(uint32_t*)(dtp + 8 * DTSTR) = pkbf(d2, d3);
        }
#pragma unroll
        for (int off = 1; off <= 2; off <<= 1) {
            dmin0 = fminf(dmin0, __shfl_xor_sync(0xFFFFFFFFu, dmin0, off));
            dmin1 = fminf(dmin1, __shfl_xor_sync(0xFFFFFFFFu, dmin1, off));
        }
        if ((lane & 3) == 0) {
            rmin[r0 * 2 + side]       = dmin0;
            rmin[(r0 + 8) * 2 + side] = dmin1;
        }
        __syncthreads();

        // ---- scan stored d~, collect in-margin candidates ----
        {
            int row = tid >> 2, cq = tid & 3;
            float thr = fminf(rmin[row * 2], rmin[row * 2 + 1]) + MARGIN;
            const char* dp = smem + SM_DT + row * DTSTR + cq * 256;
#pragma unroll
            for (int i = 0; i < 16; i++) {
                uint4 u = *(const uint4*)(dp + i * 16);
                float2 f0 = bf2f(u.x), f1 = bf2f(u.y), f2 = bf2f(u.z), f3 = bf2f(u.w);
                float gm = fminf(fminf(fminf(f0.x, f0.y), fminf(f1.x, f1.y)),
                                 fminf(fminf(f2.x, f2.y), fminf(f3.x, f3.y)));
                if (gm <= thr) {   // rare (~3%)
                    int c0 = cq * 128 + i * 8;
#define PUSH(v, col) if ((v) <= thr) { int s_ = atomicAdd(&cnt[row], 1); if (s_ < CAP) lst[row*CAP + s_] = (col); }
                    PUSH(f0.x, c0);     PUSH(f0.y, c0 + 1);
                    PUSH(f1.x, c0 + 2); PUSH(f1.y, c0 + 3);
                    PUSH(f2.x, c0 + 4); PUSH(f2.y, c0 + 5);
                    PUSH(f3.x, c0 + 6); PUSH(f3.y, c0 + 7);
#undef PUSH
                }
            }
        }
        __syncthreads();

        // ---- exact rescore: 4 threads per row ----
        {
            int row = tid >> 2, sub = tid & 3;
            int c = min(cnt[row], CAP);
            float bd = 3.4e38f;
            int   bk = 0x7FFFFFFF;
            if (c > 1) {
                const float2* xr = (const float2*)(smem + SM_XF + row * 264);
                float aa = aar[row];
                for (int s = sub; s < c; s += 4) {
                    int k = lst[row*CAP + s];
                    float de = exact_dist(xr, w, k, aa, nsf[k]);
                    if (de < bd || (de == bd && k < bk)) { bd = de; bk = k; }
                }
            }
            rb[tid] = bd;
            rk[tid] = bk;
        }
        __syncthreads();

        if (tid < TILE) {
            int c = min(cnt[tid], CAP);
            int kk;
            if (c == 1) kk = lst[tid*CAP];     // certified by margin
            else {
                float f = rb[4*tid]; int k = rk[4*tid];
#pragma unroll
                for (int s = 1; s < 4; s++) {
                    float fs = rb[4*tid + s]; int ks = rk[4*tid + s];
                    if (fs < f || (fs == f && ks < k)) { f = fs; k = ks; }
                }
                kk = k;
            }
            g_idx[t * TILE + tid] = kk;
            atomicAdd(&g_counts[kk], 1);
        }
    }
}

__global__ __launch_bounds__(512) void vq_scatter(const float* __restrict__ in,
                                                  const float* __restrict__ w,
                                                  float* __restrict__ out) {
    int tid = blockIdx.x * 512 + threadIdx.x;
    int p   = tid << 2;
    int tok = p >> 6;
    int d   = p & 63;
    int kk  = g_idx[tok];

    float4 q  = *reinterpret_cast<const float4*>(w + kk * DDIM + d);
    float4 xv = *reinterpret_cast<const float4*>(in + p);
    reinterpret_cast<float4*>(out)[tid] = q;

    float dx = q.x - xv.x, dy = q.y - xv.y, dz = q.z - xv.z, dw = q.w - xv.w;
    float s = fmaf(dx, dx, fmaf(dy, dy, fmaf(dz, dz, dw * dw)));
#pragma unroll
    for (int off = 16; off > 0; off >>= 1) s += __shfl_xor_sync(0xFFFFFFFFu, s, off);
    __shared__ float red[16];
    int lane = threadIdx.x & 31, wid = threadIdx.x >> 5;
    if (lane == 0) red[wid] = s;
    __syncthreads();
    if (wid == 0) {
        float v = (lane < 16) ? red[lane] : 0.f;
#pragma unroll
        for (int off = 8; off > 0; off >>= 1) v += __shfl_xor_sync(0xFFFFFFFFu, v, off);
        if (lane == 0) atomicAdd(&g_sumsq, (double)v);
    }
}

__global__ void vq_final(float* __restrict__ out) {
    int t = threadIdx.x;
    float c = (float)g_counts[t];
    float p = c / (float)NTOK;
    float term = p * logf(p + 1e-10f);
#pragma unroll
    for (int off = 16; off > 0; off >>= 1) term += __shfl_xor_sync(0xFFFFFFFFu, term, off);
    __shared__ float red[16];
    int lane = t & 31, wid = t >> 5;
    if (lane == 0) red[wid] = term;
    __syncthreads();
    if (t == 0) {
        float H = 0.f;
#pragma unroll
        for (int j = 0; j < 16; j++) H += red[j];
        double mean = g_sumsq / (double)NELEM;
        out[NELEM]     = (float)(1.25 * mean);
        out[NELEM + 1] = expf(-H);
    }
}

extern "C" void kernel_launch(void* const* d_in, const int* in_sizes, int n_in,
                              void* d_out, int out_size) {
    const float* in = (const float*)d_in[0];
    const float* w  = (const float*)d_in[1];
    float* out = (float*)d_out;
    (void)in_sizes; (void)n_in; (void)out_size;

    cudaFuncSetAttribute(vq_gemm, cudaFuncAttributeMaxDynamicSharedMemorySize, SM_TOTAL);

    vq_init<<<1, 512>>>();
    vq_gemm<<<GRID_GEMM, THR, SM_TOTAL>>>(in, w);
    vq_scatter<<<NELEM / 4 / 512, 512>>>(in, w, out);
    vq_final<<<1, 512>>>(out);
}

// round 14
// speedup vs baseline: 1.3256x; 1.3256x over previous
#include <cuda_runtime.h>
#include <cuda_bf16.h>
#include <cstdint>

// VectorQuantizer: R10's proven 2-pass bf16 MMA screen + certified exact fp32
// rescore, scaled to 512 threads / 256-token tiles for latency hiding.

#define NTOK   131072
#define DDIM   64
#define KCODE  512
#define HWSZ   4096
#define CHW    (64*4096)
#define NELEM  (NTOK*DDIM)

#define TILE      256
#define NTILES    512
#define GRID_GEMM 148
#define THR       512
#define MARGIN    3e-3f
#define CAP       24

// ---- dynamic smem layout (bytes) ----
#define SM_BF    0            // B frags: 8192 x uint2 = 65536
#define SM_XF    65536        // X fp32: 256 x 264B = 67584
#define SM_NS    133120       // ns fp32[512] = 2048
#define SM_CNT   135168       // int[256] = 1024
#define SM_LST   136192       // int[256][CAP] = 24576
#define SM_AA    160768       // float[256] = 1024
#define SM_RB    161792       // float[512] = 2048
#define SM_RK    163840       // int[512] = 2048
#define SM_TOTAL 165888

__device__ int    g_idx[NTOK];
__device__ int    g_counts[KCODE];
__device__ double g_sumsq;

__device__ __forceinline__ uint32_t pkbf(float a, float b) {
    __nv_bfloat162 t = __floats2bfloat162_rn(a, b);
    uint32_t u; memcpy(&u, &t, 4);
    return u;
}
__device__ __forceinline__ unsigned long long pack2(float lo, float hi) {
    unsigned long long r;
    asm("mov.b64 %0, {%1,%2};" : "=l"(r) : "f"(lo), "f"(hi));
    return r;
}
__device__ __forceinline__ void fma2(unsigned long long& d, unsigned long long a, unsigned long long b) {
    asm("fma.rn.f32x2 %0, %1, %2, %0;" : "+l"(d) : "l"(a), "l"(b));
}
__device__ __forceinline__ float2 unpack2(unsigned long long v) {
    float lo, hi;
    asm("mov.b64 {%0,%1}, %2;" : "=f"(lo), "=f"(hi) : "l"(v));
    return make_float2(lo, hi);
}
__device__ __forceinline__ void mma16816(float* c, const uint32_t* a, uint32_t b0, uint32_t b1) {
    asm volatile(
        "mma.sync.aligned.m16n8k16.row.col.f32.bf16.bf16.f32 "
        "{%0,%1,%2,%3}, {%4,%5,%6,%7}, {%8,%9}, {%0,%1,%2,%3};"
        : "+f"(c[0]), "+f"(c[1]), "+f"(c[2]), "+f"(c[3])
        : "r"(a[0]), "r"(a[1]), "r"(a[2]), "r"(a[3]), "r"(b0), "r"(b1));
}

// EXACT distance, replicating R1's instruction sequence (validated R6/R10).
__device__ __forceinline__ float exact_dist(const float2* __restrict__ xr,
                                            const float* __restrict__ w,
                                            int k, float aa, float nk) {
    const float2* wr = (const float2*)(w + k * DDIM);
    unsigned long long a0 = 0ull, a1 = 0ull, a2 = 0ull, a3 = 0ull;
#pragma unroll
    for (int j = 0; j < 8; j++) {
        float2 x0 = xr[4*j+0], x1 = xr[4*j+1], x2 = xr[4*j+2], x3 = xr[4*j+3];
        float2 w0 = wr[4*j+0], w1 = wr[4*j+1], w2 = wr[4*j+2], w3 = wr[4*j+3];
        fma2(a0, pack2(x0.x, x0.y), pack2(w0.x, w0.y));
        fma2(a1, pack2(x1.x, x1.y), pack2(w1.x, w1.y));
        fma2(a2, pack2(x2.x, x2.y), pack2(w2.x, w2.y));
        fma2(a3, pack2(x3.x, x3.y), pack2(w3.x, w3.y));
    }
    float2 f0 = unpack2(a0), f1 = unpack2(a1), f2 = unpack2(a2), f3 = unpack2(a3);
    float m = ((f0.x + f0.y) + (f1.x + f1.y)) + ((f2.x + f2.y) + (f3.x + f3.y));
    return (aa - 2.0f * m) + nk;
}

__global__ void vq_init() {
    int t = threadIdx.x;
    if (t < KCODE) g_counts[t] = 0;
    if (t == 0)    g_sumsq = 0.0;
}

extern __shared__ char smem[];

__global__ __launch_bounds__(THR, 1) void vq_gemm(const float* __restrict__ in,
                                                  const float* __restrict__ w) {
    const int tid  = threadIdx.x;
    const int warp = tid >> 5;
    const int lane = tid & 31;

    // ---- one-time staging: ns + bf16 B fragments ----
    {
        float* ns = (float*)(smem + SM_NS);
        {
            int c = tid;
            const float4* wr = (const float4*)(w + c * DDIM);
            float nrm = 0.f;
#pragma unroll
            for (int j = 0; j < 16; j++) {
                float4 v = wr[j];
                nrm = fmaf(v.x, v.x, nrm); nrm = fmaf(v.y, v.y, nrm);
                nrm = fmaf(v.z, v.z, nrm); nrm = fmaf(v.w, v.w, nrm);
            }
            ns[c] = nrm;
        }
#pragma unroll
        for (int j = 0; j < 16; j++) {
            int idx = j * 512 + tid;            // nbg*128 + kt*32 + ln
            int ln  = idx & 31;
            int kt  = (idx >> 5) & 3;
            int nbg = idx >> 7;
            int n   = nbg * 8 + (ln >> 2);
            int k0  = kt * 16 + (ln & 3) * 2;
            float2 fa = *(const float2*)(w + n * DDIM + k0);
            float2 fb = *(const float2*)(w + n * DDIM + k0 + 8);
            uint2 fr;
            fr.x = pkbf(fa.x, fa.y);
            fr.y = pkbf(fb.x, fb.y);
            *(uint2*)(smem + SM_BF + (size_t)idx * 8) = fr;
        }
    }
    __syncthreads();

    const int m  = tid & 255;                 // gather row
    const int h  = tid >> 8;                  // gather dim half
    const int r0 = warp * 16 + (lane >> 2);   // rows r0 (Lo), r0+8 (Hi)
    const float* nsf = (const float*)(smem + SM_NS);
    int*   cnt = (int*)(smem + SM_CNT);
    int*   lst = (int*)(smem + SM_LST);
    float* aar = (float*)(smem + SM_AA);
    float* rb  = (float*)(smem + SM_RB);
    int*   rk  = (int*)(smem + SM_RK);

    for (int t = blockIdx.x; t < NTILES; t += GRID_GEMM) {
        __syncthreads();   // prev tile fully consumed

        // ---- gather 256 tokens x 64 dims (fp32, exact, coalesced) ----
        {
            const int b   = t >> 4;
            const int hw0 = (t & 15) << 8;
            const float* base = in + b * CHW + hw0 + m;
            char* pf = smem + SM_XF + m * 264;
#pragma unroll
            for (int j = 0; j < 32; j += 2) {
                int d = h * 32 + j;
                float x0 = base[d * HWSZ];
                float x1 = base[(d + 1) * HWSZ];
                *(float2*)(pf + d * 4) = make_float2(x0, x1);
            }
            if (tid < TILE) cnt[tid] = 0;
        }
        __syncthreads();

        // ---- exact ||x||^2 (R1 serial order) ----
        if (tid < TILE) {
            const float2* xr = (const float2*)(smem + SM_XF + tid * 264);
            float aa = 0.f;
#pragma unroll
            for (int j = 0; j < 32; j++) {
                float2 v = xr[j];
                aa = fmaf(v.x, v.x, aa);
                aa = fmaf(v.y, v.y, aa);
            }
            aar[tid] = aa;
        }

        // ---- A fragments from fp32 X (cvt in regs) ----
        uint32_t ah[16];
        {
            const char* pxa = smem + SM_XF + r0 * 264 + (lane & 3) * 8;
#pragma unroll
            for (int kt = 0; kt < 4; kt++) {
                float2 v0 = *(const float2*)(pxa + kt * 64);
                float2 v1 = *(const float2*)(pxa + kt * 64 + 8 * 264);
                float2 v2 = *(const float2*)(pxa + kt * 64 + 32);
                float2 v3 = *(const float2*)(pxa + kt * 64 + 8 * 264 + 32);
                ah[kt*4+0] = pkbf(v0.x, v0.y);
                ah[kt*4+1] = pkbf(v1.x, v1.y);
                ah[kt*4+2] = pkbf(v2.x, v2.y);
                ah[kt*4+3] = pkbf(v3.x, v3.y);
            }
        }

        // ---- pass 1: branchless value-min screen (dual MMA chains) ----
        float dLmin = 3.4e38f, dHmin = 3.4e38f;
        for (int nc = 0; nc < 8; nc++) {
#pragma unroll
            for (int nbp = 0; nbp < 4; nbp++) {
                float c0[4] = {0.f,0.f,0.f,0.f}, c1[4] = {0.f,0.f,0.f,0.f};
                const char* f0p = smem + SM_BF + ((size_t)((nc * 8 + 2*nbp) * 128) + lane) * 8;
#pragma unroll
                for (int kt = 0; kt < 4; kt++) {
                    uint2 f0 = *(const uint2*)(f0p + kt * 256);
                    uint2 f1 = *(const uint2*)(f0p + 1024 + kt * 256);
                    mma16816(c0, ah + kt*4, f0.x, f0.y);
                    mma16816(c1, ah + kt*4, f1.x, f1.y);
                }
                int cb0 = nc * 64 + nbp * 16 + (lane & 3) * 2;
                float2 n0 = *(const float2*)(smem + SM_NS + cb0 * 4);
                float2 n1 = *(const float2*)(smem + SM_NS + (cb0 + 8) * 4);
                dLmin = fminf(dLmin, fmaf(-2.f, c0[0], n0.x));
                dLmin = fminf(dLmin, fmaf(-2.f, c0[1], n0.y));
                dHmin = fminf(dHmin, fmaf(-2.f, c0[2], n0.x));
                dHmin = fminf(dHmin, fmaf(-2.f, c0[3], n0.y));
                dLmin = fminf(dLmin, fmaf(-2.f, c1[0], n1.x));
                dLmin = fminf(dLmin, fmaf(-2.f, c1[1], n1.y));
                dHmin = fminf(dHmin, fmaf(-2.f, c1[2], n1.x));
                dHmin = fminf(dHmin, fmaf(-2.f, c1[3], n1.y));
            }
        }
#pragma unroll
        for (int off = 1; off <= 2; off <<= 1) {
            dLmin = fminf(dLmin, __shfl_xor_sync(0xFFFFFFFFu, dLmin, off));
            dHmin = fminf(dHmin, __shfl_xor_sync(0xFFFFFFFFu, dHmin, off));
        }
        const float thrL = dLmin + MARGIN;
        const float thrH = dHmin + MARGIN;

        // ---- pass 2: recompute (deterministic), collect in-margin candidates ----
        for (int nc = 0; nc < 8; nc++) {
#pragma unroll
            for (int nbp = 0; nbp < 4; nbp++) {
                float c0[4] = {0.f,0.f,0.f,0.f}, c1[4] = {0.f,0.f,0.f,0.f};
                const char* f0p = smem + SM_BF + ((size_t)((nc * 8 + 2*nbp) * 128) + lane) * 8;
#pragma unroll
                for (int kt = 0; kt < 4; kt++) {
                    uint2 f0 = *(const uint2*)(f0p + kt * 256);
                    uint2 f1 = *(const uint2*)(f0p + 1024 + kt * 256);
                    mma16816(c0, ah + kt*4, f0.x, f0.y);
                    mma16816(c1, ah + kt*4, f1.x, f1.y);
                }
                int cb0 = nc * 64 + nbp * 16 + (lane & 3) * 2;
                float2 n0 = *(const float2*)(smem + SM_NS + cb0 * 4);
                float2 n1 = *(const float2*)(smem + SM_NS + (cb0 + 8) * 4);
                float dL0 = fmaf(-2.f, c0[0], n0.x), dL1 = fmaf(-2.f, c0[1], n0.y);
                float dH0 = fmaf(-2.f, c0[2], n0.x), dH1 = fmaf(-2.f, c0[3], n0.y);
                float dL2 = fmaf(-2.f, c1[0], n1.x), dL3 = fmaf(-2.f, c1[1], n1.y);
                float dH2 = fmaf(-2.f, c1[2], n1.x), dH3 = fmaf(-2.f, c1[3], n1.y);
                bool any = (dL0 <= thrL) | (dL1 <= thrL) | (dL2 <= thrL) | (dL3 <= thrL)
                         | (dH0 <= thrH) | (dH1 <= thrH) | (dH2 <= thrH) | (dH3 <= thrH);
                if (__any_sync(0xFFFFFFFFu, any)) {
                    if (dL0 <= thrL) { int s = atomicAdd(&cnt[r0], 1);     if (s < CAP) lst[r0*CAP+s]     = cb0; }
                    if (dL1 <= thrL) { int s = atomicAdd(&cnt[r0], 1);     if (s < CAP) lst[r0*CAP+s]     = cb0+1; }
                    if (dL2 <= thrL) { int s = atomicAdd(&cnt[r0], 1);     if (s < CAP) lst[r0*CAP+s]     = cb0+8; }
                    if (dL3 <= thrL) { int s = atomicAdd(&cnt[r0], 1);     if (s < CAP) lst[r0*CAP+s]     = cb0+9; }
                    if (dH0 <= thrH) { int s = atomicAdd(&cnt[r0+8], 1);   if (s < CAP) lst[(r0+8)*CAP+s] = cb0; }
                    if (dH1 <= thrH) { int s = atomicAdd(&cnt[r0+8], 1);   if (s < CAP) lst[(r0+8)*CAP+s] = cb0+1; }
                    if (dH2 <= thrH) { int s = atomicAdd(&cnt[r0+8], 1);   if (s < CAP) lst[(r0+8)*CAP+s] = cb0+8; }
                    if (dH3 <= thrH) { int s = atomicAdd(&cnt[r0+8], 1);   if (s < CAP) lst[(r0+8)*CAP+s] = cb0+9; }
                }
            }
        }
        __syncthreads();

        // ---- exact rescore: 2 threads per row over its candidate list ----
        {
            int row = tid >> 1, sub = tid & 1;
            int c = min(cnt[row], CAP);
            float bd = 3.4e38f;
            int   bk = 0x7FFFFFFF;
            if (c > 1) {
                const float2* xr = (const float2*)(smem + SM_XF + row * 264);
                float aa = aar[row];
                for (int s = sub; s < c; s += 2) {
                    int k = lst[row*CAP + s];
                    float de = exact_dist(xr, w, k, aa, nsf[k]);
                    if (de < bd || (de == bd && k < bk)) { bd = de; bk = k; }
                }
            }
            rb[tid] = bd;
            rk[tid] = bk;
        }
        __syncthreads();

        if (tid < TILE) {
            int c = min(cnt[tid], CAP);
            int kk;
            if (c == 1) kk = lst[tid*CAP];     // certified by margin
            else {
                float f0 = rb[2*tid], f1 = rb[2*tid+1];
                int   k0 = rk[2*tid], k1 = rk[2*tid+1];
                kk = (f1 < f0 || (f1 == f0 && k1 < k0)) ? k1 : k0;
            }
            g_idx[t * TILE + tid] = kk;
            atomicAdd(&g_counts[kk], 1);
        }
    }
}

__global__ __launch_bounds__(512) void vq_scatter(const float* __restrict__ in,
                                                  const float* __restrict__ w,
                                                  float* __restrict__ out) {
    int tid = blockIdx.x * 512 + threadIdx.x;
    int p   = tid << 2;
    int tok = p >> 6;
    int d   = p & 63;
    int kk  = g_idx[tok];

    float4 q  = *reinterpret_cast<const float4*>(w + kk * DDIM + d);
    float4 xv = *reinterpret_cast<const float4*>(in + p);
    reinterpret_cast<float4*>(out)[tid] = q;

    float dx = q.x - xv.x, dy = q.y - xv.y, dz = q.z - xv.z, dw = q.w - xv.w;
    float s = fmaf(dx, dx, fmaf(dy, dy, fmaf(dz, dz, dw * dw)));
#pragma unroll
    for (int off = 16; off > 0; off >>= 1) s += __shfl_xor_sync(0xFFFFFFFFu, s, off);
    __shared__ float red[16];
    int lane = threadIdx.x & 31, wid = threadIdx.x >> 5;
    if (lane == 0) red[wid] = s;
    __syncthreads();
    if (wid == 0) {
        float v = (lane < 16) ? red[lane] : 0.f;
#pragma unroll
        for (int off = 8; off > 0; off >>= 1) v += __shfl_xor_sync(0xFFFFFFFFu, v, off);
        if (lane == 0) atomicAdd(&g_sumsq, (double)v);
    }
}

__global__ void vq_final(float* __restrict__ out) {
    int t = threadIdx.x;
    float c = (float)g_counts[t];
    float p = c / (float)NTOK;
    float term = p * logf(p + 1e-10f);
#pragma unroll
    for (int off = 16; off > 0; off >>= 1) term += __shfl_xor_sync(0xFFFFFFFFu, term, off);
    __shared__ float red[16];
    int lane = t & 31, wid = t >> 5;
    if (lane == 0) red[wid] = term;
    __syncthreads();
    if (t == 0) {
        float H = 0.f;
#pragma unroll
        for (int j = 0; j < 16; j++) H += red[j];
        double mean = g_sumsq / (double)NELEM;
        out[NELEM]     = (float)(1.25 * mean);
        out[NELEM + 1] = expf(-H);
    }
}

extern "C" void kernel_launch(void* const* d_in, const int* in_sizes, int n_in,
                              void* d_out, int out_size) {
    const float* in = (const float*)d_in[0];
    const float* w  = (const float*)d_in[1];
    float* out = (float*)d_out;
    (void)in_sizes; (void)n_in; (void)out_size;

    cudaFuncSetAttribute(vq_gemm, cudaFuncAttributeMaxDynamicSharedMemorySize, SM_TOTAL);

    vq_init<<<1, 512>>>();
    vq_gemm<<<GRID_GEMM, THR, SM_TOTAL>>>(in, w);
    vq_scatter<<<NELEM / 4 / 512, 512>>>(in, w, out);
    vq_final<<<1, 512>>>(out);
}